// round 5
// baseline (speedup 1.0000x reference)
#include <cuda_runtime.h>
#include <math.h>

#define NN 100000
#define NE 3200000
#define F_IN 256
#define HID 16
#define NC 32
#define NSCB 98          // ceil(NN/1024) scan blocks

typedef unsigned long long ull;

// scratch (device globals; allocation is forbidden)
__device__ float  g_xs01[NN * 32];   // [xs0(16) | xs1(16)] per node
__device__ float  g_xroot[NN * 16];
__device__ float  g_h[NN * 16];
__device__ int    g_cnt[NN];
__device__ int    g_off[NN];
__device__ int    g_cur[NN];
__device__ float  g_inv[NN];
__device__ float2 g_edges[NE];       // {src as int bits, u}
__device__ int    g_bsum[NSCB];
__device__ int    g_boff[NSCB];

// ---------------------------------------------------------------------------
__global__ __launch_bounds__(256) void zero_kernel() {
    int i = blockIdx.x * 256 + threadIdx.x;
    if (i < NN) g_cnt[i] = 0;
}

// histogram of dst
__global__ __launch_bounds__(256) void hist_kernel(const int* __restrict__ ei) {
    int e = blockIdx.x * 256 + threadIdx.x;
    if (e >= NE) return;
    atomicAdd(&g_cnt[ei[NE + e]], 1);
}

// block sums (1024 elems per block)
__global__ __launch_bounds__(256) void scanA_kernel() {
    __shared__ int sh[256];
    int b = blockIdx.x, t = threadIdx.x;
    int base = b * 1024 + t * 4;
    int s = 0;
#pragma unroll
    for (int j = 0; j < 4; j++)
        if (base + j < NN) s += g_cnt[base + j];
    sh[t] = s;
    __syncthreads();
    for (int o = 128; o; o >>= 1) {
        if (t < o) sh[t] += sh[t + o];
        __syncthreads();
    }
    if (t == 0) g_bsum[b] = sh[0];
}

// exclusive scan of the 98 block sums — one warp, 4 elems/lane
__global__ void scanB_kernel() {
    int lane = threadIdx.x;
    int v[4], s = 0;
#pragma unroll
    for (int j = 0; j < 4; j++) {
        int i = lane * 4 + j;
        v[j] = (i < NSCB) ? g_bsum[i] : 0;
        s += v[j];
    }
    int x = s;
#pragma unroll
    for (int o = 1; o < 32; o <<= 1) {
        int y = __shfl_up_sync(0xffffffffu, x, o);
        if (lane >= o) x += y;
    }
    int excl = x - s;
#pragma unroll
    for (int j = 0; j < 4; j++) {
        int i = lane * 4 + j;
        if (i < NSCB) g_boff[i] = excl;
        excl += v[j];
    }
}

// final offsets + inv-degree
__global__ __launch_bounds__(256) void scanC_kernel() {
    int b = blockIdx.x, t = threadIdx.x;
    int base = b * 1024 + t * 4;
    int v[4], pre[4];
    int s = 0;
#pragma unroll
    for (int j = 0; j < 4; j++) {
        v[j] = (base + j < NN) ? g_cnt[base + j] : 0;
        pre[j] = s; s += v[j];
    }
    int lane = t & 31, w = t >> 5;
    int x = s;
#pragma unroll
    for (int o = 1; o < 32; o <<= 1) {
        int y = __shfl_up_sync(0xffffffffu, x, o);
        if (lane >= o) x += y;
    }
    __shared__ int wsum[8];
    if (lane == 31) wsum[w] = x;
    __syncthreads();
    if (t == 0) {
        int a = 0;
        for (int i = 0; i < 8; i++) { int tmp = wsum[i]; wsum[i] = a; a += tmp; }
    }
    __syncthreads();
    int excl = x - s + wsum[w] + g_boff[b];
#pragma unroll
    for (int j = 0; j < 4; j++) {
        if (base + j < NN) {
            int o = excl + pre[j];
            g_off[base + j] = o;
            g_cur[base + j] = o;
            g_inv[base + j] = 1.f / fmaxf((float)v[j], 1.f);
        }
    }
}

// scatter edges into CSR segments
__global__ __launch_bounds__(256) void scatter_kernel(
    const int* __restrict__ ei, const float* __restrict__ ea) {
    int e = blockIdx.x * 256 + threadIdx.x;
    if (e >= NE) return;
    int s = ei[e];
    int d = ei[NE + e];
    float u = fminf(fmaxf(ea[e], 0.f), 1.f);
    int slot = atomicAdd(&g_cur[d], 1);
    g_edges[slot] = make_float2(__int_as_float(s), u);
}

// ---------------------------------------------------------------------------
// GEMM1 with packed f32x2 FMA, weights pre-duplicated in smem.
// [xs0|xs1] -> g_xs01, root part -> g_xroot
__global__ __launch_bounds__(256) void gemm1_kernel(
    const float* __restrict__ x, const float* __restrict__ W1,
    const float* __restrict__ root1) {
    __shared__ float  xt[64][132];       // [k][node]
    __shared__ float2 wc2[64][48];       // [k][col] duplicated {w,w}

    const int tid = threadIdx.x;
    const int cg  = tid & 7;             // col group: cols cg*6..cg*6+5
    const int ng  = tid >> 3;            // node group: nodes ng*4..ng*4+3
    const int n0  = blockIdx.x * 128;

    ull acc01[6], acc23[6];
#pragma unroll
    for (int i = 0; i < 6; i++) { acc01[i] = 0ull; acc23[i] = 0ull; }

    for (int k0 = 0; k0 < F_IN; k0 += 64) {
        // stage x transposed
        {
            int nl = tid >> 1;
            int n  = n0 + nl;
            int half = tid & 1;
#pragma unroll
            for (int i = 0; i < 8; i++) {
                int q = half * 8 + i;
                float4 v = make_float4(0.f, 0.f, 0.f, 0.f);
                if (n < NN)
                    v = *(const float4*)(x + (size_t)n * F_IN + k0 + q * 4);
                xt[q * 4 + 0][nl] = v.x;
                xt[q * 4 + 1][nl] = v.y;
                xt[q * 4 + 2][nl] = v.z;
                xt[q * 4 + 3][nl] = v.w;
            }
        }
        // stage weights duplicated
        for (int i = tid; i < 64 * 48; i += 256) {
            int kk = i / 48, c = i % 48;
            int f = k0 + kk;
            float w;
            if (c < 32) w = W1[(c >> 4) * (F_IN * HID) + f * HID + (c & 15)];
            else        w = root1[f * HID + (c - 32)];
            wc2[kk][c] = make_float2(w, w);
        }
        __syncthreads();

#pragma unroll 4
        for (int kk = 0; kk < 64; kk++) {
            const ull* xp = (const ull*)&xt[kk][ng * 4];
            ull xa = xp[0], xb = xp[1];
            const ulonglong2* wp = (const ulonglong2*)&wc2[kk][cg * 6];
            ulonglong2 wA = wp[0], wB = wp[1], wC = wp[2];
            asm("fma.rn.f32x2 %0, %1, %2, %0;" : "+l"(acc01[0]) : "l"(xa), "l"(wA.x));
            asm("fma.rn.f32x2 %0, %1, %2, %0;" : "+l"(acc23[0]) : "l"(xb), "l"(wA.x));
            asm("fma.rn.f32x2 %0, %1, %2, %0;" : "+l"(acc01[1]) : "l"(xa), "l"(wA.y));
            asm("fma.rn.f32x2 %0, %1, %2, %0;" : "+l"(acc23[1]) : "l"(xb), "l"(wA.y));
            asm("fma.rn.f32x2 %0, %1, %2, %0;" : "+l"(acc01[2]) : "l"(xa), "l"(wB.x));
            asm("fma.rn.f32x2 %0, %1, %2, %0;" : "+l"(acc23[2]) : "l"(xb), "l"(wB.x));
            asm("fma.rn.f32x2 %0, %1, %2, %0;" : "+l"(acc01[3]) : "l"(xa), "l"(wB.y));
            asm("fma.rn.f32x2 %0, %1, %2, %0;" : "+l"(acc23[3]) : "l"(xb), "l"(wB.y));
            asm("fma.rn.f32x2 %0, %1, %2, %0;" : "+l"(acc01[4]) : "l"(xa), "l"(wC.x));
            asm("fma.rn.f32x2 %0, %1, %2, %0;" : "+l"(acc23[4]) : "l"(xb), "l"(wC.x));
            asm("fma.rn.f32x2 %0, %1, %2, %0;" : "+l"(acc01[5]) : "l"(xa), "l"(wC.y));
            asm("fma.rn.f32x2 %0, %1, %2, %0;" : "+l"(acc23[5]) : "l"(xb), "l"(wC.y));
        }
        __syncthreads();
    }

#pragma unroll
    for (int j = 0; j < 6; j++) {
        float v0, v1, v2, v3;
        asm("mov.b64 {%0, %1}, %2;" : "=f"(v0), "=f"(v1) : "l"(acc01[j]));
        asm("mov.b64 {%0, %1}, %2;" : "=f"(v2), "=f"(v3) : "l"(acc23[j]));
        float vals[4] = {v0, v1, v2, v3};
        int c = cg * 6 + j;
#pragma unroll
        for (int v = 0; v < 4; v++) {
            int n = n0 + ng * 4 + v;
            if (n < NN) {
                if (c < 32) g_xs01[(size_t)n * 32 + c] = vals[v];
                else        g_xroot[(size_t)n * 16 + (c - 32)] = vals[v];
            }
        }
    }
}

// ---------------------------------------------------------------------------
// Pull pass 1 + node update: warp per dst node, half-warp streams, 2x unroll
// (2 edges per stream-iter, 2-deep prefetch -> 4 gathers in flight per warp).
__global__ __launch_bounds__(256) void pass1_kernel(const float* __restrict__ bias1) {
    int n = blockIdx.x * 8 + (threadIdx.x >> 5);
    if (n >= NN) return;
    int lane = threadIdx.x & 31;
    int f = lane & 15, half = lane >> 4;
    int beg = g_off[n];
    int deg = g_cnt[n];

    const float2 z = make_float2(0.f, 0.f);
    float accA = 0.f, accB = 0.f;
    float2 e0 = (half < deg)     ? g_edges[beg + half]     : z;
    float2 e1 = (half + 2 < deg) ? g_edges[beg + half + 2] : z;
    for (int i = half; i < deg; i += 4) {
        float2 p0 = (i + 4 < deg) ? g_edges[beg + i + 4] : z;
        float2 p1 = (i + 6 < deg) ? g_edges[beg + i + 6] : z;
        {
            int s = __float_as_int(e0.x);
            float u = e0.y;
            const float* p = g_xs01 + (size_t)s * 32;
            accA += (1.f - u) * __ldg(p + f) + u * __ldg(p + 16 + f);
        }
        if (i + 2 < deg) {
            int s = __float_as_int(e1.x);
            float u = e1.y;
            const float* p = g_xs01 + (size_t)s * 32;
            accB += (1.f - u) * __ldg(p + f) + u * __ldg(p + 16 + f);
        }
        e0 = p0; e1 = p1;
    }
    float acc = accA + accB;
    acc += __shfl_xor_sync(0xffffffffu, acc, 16);
    if (half == 0) {
        float v = acc * g_inv[n] + g_xroot[(size_t)n * 16 + f] + bias1[f];
        g_h[(size_t)n * 16 + f] = v > 0.f ? v : expm1f(v);
    }
}

// ---------------------------------------------------------------------------
// Pull pass 2 + final GEMM + log_softmax, same 2x stream unroll.
__global__ __launch_bounds__(256) void pass2_final_kernel(
    const float* __restrict__ W2, const float* __restrict__ root2,
    const float* __restrict__ bias2, float* __restrict__ out) {
    const int lane = threadIdx.x & 31;
    const int f = lane & 15, half = lane >> 4;
    const int wid = blockIdx.x * 8 + (threadIdx.x >> 5);
    const int nwarps = gridDim.x * 8;

    float w0col[16], w1col[16], rcol[16];
#pragma unroll
    for (int k = 0; k < 16; k++) {
        w0col[k] = W2[k * NC + lane];
        w1col[k] = W2[16 * NC + k * NC + lane];
        rcol[k]  = root2[k * NC + lane];
    }
    const float bias = bias2[lane];
    const float2 z = make_float2(0.f, 0.f);

    for (int n = wid; n < NN; n += nwarps) {
        int beg = g_off[n];
        int deg = g_cnt[n];
        float a0A = 0.f, a1A = 0.f, a0B = 0.f, a1B = 0.f;
        float2 e0 = (half < deg)     ? g_edges[beg + half]     : z;
        float2 e1 = (half + 2 < deg) ? g_edges[beg + half + 2] : z;
        for (int i = half; i < deg; i += 4) {
            float2 p0 = (i + 4 < deg) ? g_edges[beg + i + 4] : z;
            float2 p1 = (i + 6 < deg) ? g_edges[beg + i + 6] : z;
            {
                int s = __float_as_int(e0.x);
                float u = e0.y;
                float hv = __ldg(g_h + (size_t)s * 16 + f);
                a0A += (1.f - u) * hv;
                a1A += u * hv;
            }
            if (i + 2 < deg) {
                int s = __float_as_int(e1.x);
                float u = e1.y;
                float hv = __ldg(g_h + (size_t)s * 16 + f);
                a0B += (1.f - u) * hv;
                a1B += u * hv;
            }
            e0 = p0; e1 = p1;
        }
        float a0 = a0A + a0B, a1 = a1A + a1B;
        a0 += __shfl_xor_sync(0xffffffffu, a0, 16);
        a1 += __shfl_xor_sync(0xffffffffu, a1, 16);
        float hn = g_h[(size_t)n * 16 + f];

        float oagg = 0.f, oroot = 0.f;
#pragma unroll
        for (int k = 0; k < 16; k++) {
            float a0k = __shfl_sync(0xffffffffu, a0, k);
            float a1k = __shfl_sync(0xffffffffu, a1, k);
            float hk  = __shfl_sync(0xffffffffu, hn, k);
            oagg  += a0k * w0col[k] + a1k * w1col[k];
            oroot += hk * rcol[k];
        }
        float o = oagg * g_inv[n] + oroot + bias;

        float m = o;
#pragma unroll
        for (int off = 16; off; off >>= 1)
            m = fmaxf(m, __shfl_xor_sync(0xffffffffu, m, off));
        float ex = __expf(o - m);
        float ssum = ex;
#pragma unroll
        for (int off = 16; off; off >>= 1)
            ssum += __shfl_xor_sync(0xffffffffu, ssum, off);
        out[(size_t)n * 32 + lane] = o - m - logf(ssum);
    }
}

// ---------------------------------------------------------------------------
extern "C" void kernel_launch(void* const* d_in, const int* in_sizes, int n_in,
                              void* d_out, int out_size) {
    const float* x     = (const float*)d_in[0];
    const float* ea    = (const float*)d_in[1];
    const float* W1    = (const float*)d_in[2];
    const float* root1 = (const float*)d_in[3];
    const float* bias1 = (const float*)d_in[4];
    const float* W2    = (const float*)d_in[5];
    const float* root2 = (const float*)d_in[6];
    const float* bias2 = (const float*)d_in[7];
    const int*   ei    = (const int*)d_in[8];
    float* out = (float*)d_out;

    zero_kernel<<<(NN + 255) / 256, 256>>>();
    hist_kernel<<<(NE + 255) / 256, 256>>>(ei);
    scanA_kernel<<<NSCB, 256>>>();
    gemm1_kernel<<<(NN + 127) / 128, 256>>>(x, W1, root1);  // profiled slot (#3)
    scanB_kernel<<<1, 32>>>();
    scanC_kernel<<<NSCB, 256>>>();
    scatter_kernel<<<(NE + 255) / 256, 256>>>(ei, ea);
    pass1_kernel<<<(NN + 7) / 8, 256>>>(bias1);
    pass2_final_kernel<<<1850, 256>>>(W2, root2, bias2, out);
}

// round 6
// speedup vs baseline: 1.0107x; 1.0107x over previous
#include <cuda_runtime.h>
#include <math.h>

#define NN 100000
#define NE 3200000
#define F_IN 256
#define HID 16
#define NC 32
#define NSCB 98          // ceil(NN/1024) scan blocks

typedef unsigned long long ull;

// scratch (device globals; allocation is forbidden)
__device__ float  g_xs01[NN * 32];   // [xs0(16) | xs1(16)] per node
__device__ float  g_xroot[NN * 16];
__device__ float  g_h[NN * 16];
__device__ int    g_cnt[NN];
__device__ int    g_off[NN];
__device__ int    g_cur[NN];
__device__ float  g_inv[NN];
__device__ float2 g_edges[NE];       // {src as int bits, u}
__device__ int    g_bsum[NSCB];
__device__ int    g_boff[NSCB];

// ---------------------------------------------------------------------------
__global__ __launch_bounds__(256) void zero_kernel() {
    int i = blockIdx.x * 256 + threadIdx.x;
    if (i < NN) g_cnt[i] = 0;
}

// histogram of dst
__global__ __launch_bounds__(256) void hist_kernel(const int* __restrict__ ei) {
    int e = blockIdx.x * 256 + threadIdx.x;
    if (e >= NE) return;
    atomicAdd(&g_cnt[ei[NE + e]], 1);
}

// block sums (1024 elems per block)
__global__ __launch_bounds__(256) void scanA_kernel() {
    __shared__ int sh[256];
    int b = blockIdx.x, t = threadIdx.x;
    int base = b * 1024 + t * 4;
    int s = 0;
#pragma unroll
    for (int j = 0; j < 4; j++)
        if (base + j < NN) s += g_cnt[base + j];
    sh[t] = s;
    __syncthreads();
    for (int o = 128; o; o >>= 1) {
        if (t < o) sh[t] += sh[t + o];
        __syncthreads();
    }
    if (t == 0) g_bsum[b] = sh[0];
}

// exclusive scan of the 98 block sums — one warp, 4 elems/lane
__global__ void scanB_kernel() {
    int lane = threadIdx.x;
    int v[4], s = 0;
#pragma unroll
    for (int j = 0; j < 4; j++) {
        int i = lane * 4 + j;
        v[j] = (i < NSCB) ? g_bsum[i] : 0;
        s += v[j];
    }
    int x = s;
#pragma unroll
    for (int o = 1; o < 32; o <<= 1) {
        int y = __shfl_up_sync(0xffffffffu, x, o);
        if (lane >= o) x += y;
    }
    int excl = x - s;
#pragma unroll
    for (int j = 0; j < 4; j++) {
        int i = lane * 4 + j;
        if (i < NSCB) g_boff[i] = excl;
        excl += v[j];
    }
}

// final offsets + inv-degree
__global__ __launch_bounds__(256) void scanC_kernel() {
    int b = blockIdx.x, t = threadIdx.x;
    int base = b * 1024 + t * 4;
    int v[4], pre[4];
    int s = 0;
#pragma unroll
    for (int j = 0; j < 4; j++) {
        v[j] = (base + j < NN) ? g_cnt[base + j] : 0;
        pre[j] = s; s += v[j];
    }
    int lane = t & 31, w = t >> 5;
    int x = s;
#pragma unroll
    for (int o = 1; o < 32; o <<= 1) {
        int y = __shfl_up_sync(0xffffffffu, x, o);
        if (lane >= o) x += y;
    }
    __shared__ int wsum[8];
    if (lane == 31) wsum[w] = x;
    __syncthreads();
    if (t == 0) {
        int a = 0;
        for (int i = 0; i < 8; i++) { int tmp = wsum[i]; wsum[i] = a; a += tmp; }
    }
    __syncthreads();
    int excl = x - s + wsum[w] + g_boff[b];
#pragma unroll
    for (int j = 0; j < 4; j++) {
        if (base + j < NN) {
            int o = excl + pre[j];
            g_off[base + j] = o;
            g_cur[base + j] = o;
            g_inv[base + j] = 1.f / fmaxf((float)v[j], 1.f);
        }
    }
}

// scatter edges into CSR segments
__global__ __launch_bounds__(256) void scatter_kernel(
    const int* __restrict__ ei, const float* __restrict__ ea) {
    int e = blockIdx.x * 256 + threadIdx.x;
    if (e >= NE) return;
    int s = ei[e];
    int d = ei[NE + e];
    float u = fminf(fmaxf(ea[e], 0.f), 1.f);
    int slot = atomicAdd(&g_cur[d], 1);
    g_edges[slot] = make_float2(__int_as_float(s), u);
}

// ---------------------------------------------------------------------------
// GEMM1, f32x2 FMA, K-chunk 32 (smem 29KB -> 7 blocks/SM, occ ~87%).
// [xs0|xs1] -> g_xs01, root part -> g_xroot
__global__ __launch_bounds__(256) void gemm1_kernel(
    const float* __restrict__ x, const float* __restrict__ W1,
    const float* __restrict__ root1) {
    __shared__ float  xt[32][132];       // [k][node]
    __shared__ float2 wc2[32][48];       // [k][col] duplicated {w,w}

    const int tid = threadIdx.x;
    const int cg  = tid & 7;             // col group: cols cg*6..cg*6+5
    const int ng  = tid >> 3;            // node group: nodes ng*4..ng*4+3
    const int n0  = blockIdx.x * 128;

    ull acc01[6], acc23[6];
#pragma unroll
    for (int i = 0; i < 6; i++) { acc01[i] = 0ull; acc23[i] = 0ull; }

    for (int k0 = 0; k0 < F_IN; k0 += 32) {
        // stage x transposed: 128 nodes x 32 k
        {
            int nl = tid >> 1;
            int n  = n0 + nl;
            int half = tid & 1;
#pragma unroll
            for (int i = 0; i < 4; i++) {
                int q = half * 4 + i;
                float4 v = make_float4(0.f, 0.f, 0.f, 0.f);
                if (n < NN)
                    v = *(const float4*)(x + (size_t)n * F_IN + k0 + q * 4);
                xt[q * 4 + 0][nl] = v.x;
                xt[q * 4 + 1][nl] = v.y;
                xt[q * 4 + 2][nl] = v.z;
                xt[q * 4 + 3][nl] = v.w;
            }
        }
        // stage weights duplicated: 32 x 48
        for (int i = tid; i < 32 * 48; i += 256) {
            int kk = i / 48, c = i % 48;
            int f = k0 + kk;
            float w;
            if (c < 32) w = W1[(c >> 4) * (F_IN * HID) + f * HID + (c & 15)];
            else        w = root1[f * HID + (c - 32)];
            wc2[kk][c] = make_float2(w, w);
        }
        __syncthreads();

#pragma unroll 4
        for (int kk = 0; kk < 32; kk++) {
            const ull* xp = (const ull*)&xt[kk][ng * 4];
            ull xa = xp[0], xb = xp[1];
            const ulonglong2* wp = (const ulonglong2*)&wc2[kk][cg * 6];
            ulonglong2 wA = wp[0], wB = wp[1], wC = wp[2];
            asm("fma.rn.f32x2 %0, %1, %2, %0;" : "+l"(acc01[0]) : "l"(xa), "l"(wA.x));
            asm("fma.rn.f32x2 %0, %1, %2, %0;" : "+l"(acc23[0]) : "l"(xb), "l"(wA.x));
            asm("fma.rn.f32x2 %0, %1, %2, %0;" : "+l"(acc01[1]) : "l"(xa), "l"(wA.y));
            asm("fma.rn.f32x2 %0, %1, %2, %0;" : "+l"(acc23[1]) : "l"(xb), "l"(wA.y));
            asm("fma.rn.f32x2 %0, %1, %2, %0;" : "+l"(acc01[2]) : "l"(xa), "l"(wB.x));
            asm("fma.rn.f32x2 %0, %1, %2, %0;" : "+l"(acc23[2]) : "l"(xb), "l"(wB.x));
            asm("fma.rn.f32x2 %0, %1, %2, %0;" : "+l"(acc01[3]) : "l"(xa), "l"(wB.y));
            asm("fma.rn.f32x2 %0, %1, %2, %0;" : "+l"(acc23[3]) : "l"(xb), "l"(wB.y));
            asm("fma.rn.f32x2 %0, %1, %2, %0;" : "+l"(acc01[4]) : "l"(xa), "l"(wC.x));
            asm("fma.rn.f32x2 %0, %1, %2, %0;" : "+l"(acc23[4]) : "l"(xb), "l"(wC.x));
            asm("fma.rn.f32x2 %0, %1, %2, %0;" : "+l"(acc01[5]) : "l"(xa), "l"(wC.y));
            asm("fma.rn.f32x2 %0, %1, %2, %0;" : "+l"(acc23[5]) : "l"(xb), "l"(wC.y));
        }
        __syncthreads();
    }

#pragma unroll
    for (int j = 0; j < 6; j++) {
        float v0, v1, v2, v3;
        asm("mov.b64 {%0, %1}, %2;" : "=f"(v0), "=f"(v1) : "l"(acc01[j]));
        asm("mov.b64 {%0, %1}, %2;" : "=f"(v2), "=f"(v3) : "l"(acc23[j]));
        float vals[4] = {v0, v1, v2, v3};
        int c = cg * 6 + j;
#pragma unroll
        for (int v = 0; v < 4; v++) {
            int n = n0 + ng * 4 + v;
            if (n < NN) {
                if (c < 32) g_xs01[(size_t)n * 32 + c] = vals[v];
                else        g_xroot[(size_t)n * 16 + (c - 32)] = vals[v];
            }
        }
    }
}

// ---------------------------------------------------------------------------
// Pull pass 1 + node update: warp per dst node, half-warp streams, 2x unroll.
__global__ __launch_bounds__(256) void pass1_kernel(const float* __restrict__ bias1) {
    int n = blockIdx.x * 8 + (threadIdx.x >> 5);
    if (n >= NN) return;
    int lane = threadIdx.x & 31;
    int f = lane & 15, half = lane >> 4;
    int beg = g_off[n];
    int deg = g_cnt[n];

    const float2 z = make_float2(0.f, 0.f);
    float accA = 0.f, accB = 0.f;
    float2 e0 = (half < deg)     ? g_edges[beg + half]     : z;
    float2 e1 = (half + 2 < deg) ? g_edges[beg + half + 2] : z;
    for (int i = half; i < deg; i += 4) {
        float2 p0 = (i + 4 < deg) ? g_edges[beg + i + 4] : z;
        float2 p1 = (i + 6 < deg) ? g_edges[beg + i + 6] : z;
        {
            int s = __float_as_int(e0.x);
            float u = e0.y;
            const float* p = g_xs01 + (size_t)s * 32;
            accA += (1.f - u) * __ldg(p + f) + u * __ldg(p + 16 + f);
        }
        if (i + 2 < deg) {
            int s = __float_as_int(e1.x);
            float u = e1.y;
            const float* p = g_xs01 + (size_t)s * 32;
            accB += (1.f - u) * __ldg(p + f) + u * __ldg(p + 16 + f);
        }
        e0 = p0; e1 = p1;
    }
    float acc = accA + accB;
    acc += __shfl_xor_sync(0xffffffffu, acc, 16);
    if (half == 0) {
        float v = acc * g_inv[n] + g_xroot[(size_t)n * 16 + f] + bias1[f];
        g_h[(size_t)n * 16 + f] = v > 0.f ? v : expm1f(v);
    }
}

// ---------------------------------------------------------------------------
// Pull pass 2 + final GEMM + log_softmax, same 2x stream unroll.
__global__ __launch_bounds__(256) void pass2_final_kernel(
    const float* __restrict__ W2, const float* __restrict__ root2,
    const float* __restrict__ bias2, float* __restrict__ out) {
    const int lane = threadIdx.x & 31;
    const int f = lane & 15, half = lane >> 4;
    const int wid = blockIdx.x * 8 + (threadIdx.x >> 5);
    const int nwarps = gridDim.x * 8;

    float w0col[16], w1col[16], rcol[16];
#pragma unroll
    for (int k = 0; k < 16; k++) {
        w0col[k] = W2[k * NC + lane];
        w1col[k] = W2[16 * NC + k * NC + lane];
        rcol[k]  = root2[k * NC + lane];
    }
    const float bias = bias2[lane];
    const float2 z = make_float2(0.f, 0.f);

    for (int n = wid; n < NN; n += nwarps) {
        int beg = g_off[n];
        int deg = g_cnt[n];
        float a0A = 0.f, a1A = 0.f, a0B = 0.f, a1B = 0.f;
        float2 e0 = (half < deg)     ? g_edges[beg + half]     : z;
        float2 e1 = (half + 2 < deg) ? g_edges[beg + half + 2] : z;
        for (int i = half; i < deg; i += 4) {
            float2 p0 = (i + 4 < deg) ? g_edges[beg + i + 4] : z;
            float2 p1 = (i + 6 < deg) ? g_edges[beg + i + 6] : z;
            {
                int s = __float_as_int(e0.x);
                float u = e0.y;
                float hv = __ldg(g_h + (size_t)s * 16 + f);
                a0A += (1.f - u) * hv;
                a1A += u * hv;
            }
            if (i + 2 < deg) {
                int s = __float_as_int(e1.x);
                float u = e1.y;
                float hv = __ldg(g_h + (size_t)s * 16 + f);
                a0B += (1.f - u) * hv;
                a1B += u * hv;
            }
            e0 = p0; e1 = p1;
        }
        float a0 = a0A + a0B, a1 = a1A + a1B;
        a0 += __shfl_xor_sync(0xffffffffu, a0, 16);
        a1 += __shfl_xor_sync(0xffffffffu, a1, 16);
        float hn = g_h[(size_t)n * 16 + f];

        float oagg = 0.f, oroot = 0.f;
#pragma unroll
        for (int k = 0; k < 16; k++) {
            float a0k = __shfl_sync(0xffffffffu, a0, k);
            float a1k = __shfl_sync(0xffffffffu, a1, k);
            float hk  = __shfl_sync(0xffffffffu, hn, k);
            oagg  += a0k * w0col[k] + a1k * w1col[k];
            oroot += hk * rcol[k];
        }
        float o = oagg * g_inv[n] + oroot + bias;

        float m = o;
#pragma unroll
        for (int off = 16; off; off >>= 1)
            m = fmaxf(m, __shfl_xor_sync(0xffffffffu, m, off));
        float ex = __expf(o - m);
        float ssum = ex;
#pragma unroll
        for (int off = 16; off; off >>= 1)
            ssum += __shfl_xor_sync(0xffffffffu, ssum, off);
        out[(size_t)n * 32 + lane] = o - m - logf(ssum);
    }
}

// ---------------------------------------------------------------------------
extern "C" void kernel_launch(void* const* d_in, const int* in_sizes, int n_in,
                              void* d_out, int out_size) {
    const float* x     = (const float*)d_in[0];
    const float* ea    = (const float*)d_in[1];
    const float* W1    = (const float*)d_in[2];
    const float* root1 = (const float*)d_in[3];
    const float* bias1 = (const float*)d_in[4];
    const float* W2    = (const float*)d_in[5];
    const float* root2 = (const float*)d_in[6];
    const float* bias2 = (const float*)d_in[7];
    const int*   ei    = (const int*)d_in[8];
    float* out = (float*)d_out;

    zero_kernel<<<(NN + 255) / 256, 256>>>();
    hist_kernel<<<(NE + 255) / 256, 256>>>(ei);
    scanA_kernel<<<NSCB, 256>>>();
    gemm1_kernel<<<(NN + 127) / 128, 256>>>(x, W1, root1);  // profiled slot (#4)
    scanB_kernel<<<1, 32>>>();
    scanC_kernel<<<NSCB, 256>>>();
    scatter_kernel<<<(NE + 255) / 256, 256>>>(ei, ea);
    pass1_kernel<<<(NN + 7) / 8, 256>>>(bias1);
    pass2_final_kernel<<<1850, 256>>>(W2, root2, bias2, out);
}

// round 7
// speedup vs baseline: 1.1867x; 1.1741x over previous
#include <cuda_runtime.h>
#include <math.h>

#define NN 100000
#define NE 3200000
#define F_IN 256
#define HID 16
#define NC 32
#define NSCB 98          // ceil(NN/1024) scan blocks

// scratch (device globals; allocation is forbidden)
__device__ float  g_xs01[NN * 32];   // [xs0(16) | xs1(16)] per node
__device__ float  g_xroot[NN * 16];
__device__ float  g_h[NN * 16];
__device__ int    g_cnt[NN];
__device__ int    g_off[NN];
__device__ int    g_cur[NN];
__device__ float  g_inv[NN];
__device__ float2 g_edges[NE];       // {src as int bits, u}
__device__ int    g_bsum[NSCB];
__device__ int    g_boff[NSCB];

// ---------------------------------------------------------------------------
__global__ __launch_bounds__(256) void zero_kernel() {
    int i = blockIdx.x * 256 + threadIdx.x;
    if (i < NN) g_cnt[i] = 0;
}

// histogram of dst
__global__ __launch_bounds__(256) void hist_kernel(const int* __restrict__ ei) {
    int e = blockIdx.x * 256 + threadIdx.x;
    if (e >= NE) return;
    atomicAdd(&g_cnt[ei[NE + e]], 1);
}

// block sums (1024 elems per block)
__global__ __launch_bounds__(256) void scanA_kernel() {
    __shared__ int sh[256];
    int b = blockIdx.x, t = threadIdx.x;
    int base = b * 1024 + t * 4;
    int s = 0;
#pragma unroll
    for (int j = 0; j < 4; j++)
        if (base + j < NN) s += g_cnt[base + j];
    sh[t] = s;
    __syncthreads();
    for (int o = 128; o; o >>= 1) {
        if (t < o) sh[t] += sh[t + o];
        __syncthreads();
    }
    if (t == 0) g_bsum[b] = sh[0];
}

// exclusive scan of the 98 block sums — one warp, 4 elems/lane
__global__ void scanB_kernel() {
    int lane = threadIdx.x;
    int v[4], s = 0;
#pragma unroll
    for (int j = 0; j < 4; j++) {
        int i = lane * 4 + j;
        v[j] = (i < NSCB) ? g_bsum[i] : 0;
        s += v[j];
    }
    int x = s;
#pragma unroll
    for (int o = 1; o < 32; o <<= 1) {
        int y = __shfl_up_sync(0xffffffffu, x, o);
        if (lane >= o) x += y;
    }
    int excl = x - s;
#pragma unroll
    for (int j = 0; j < 4; j++) {
        int i = lane * 4 + j;
        if (i < NSCB) g_boff[i] = excl;
        excl += v[j];
    }
}

// final offsets + inv-degree
__global__ __launch_bounds__(256) void scanC_kernel() {
    int b = blockIdx.x, t = threadIdx.x;
    int base = b * 1024 + t * 4;
    int v[4], pre[4];
    int s = 0;
#pragma unroll
    for (int j = 0; j < 4; j++) {
        v[j] = (base + j < NN) ? g_cnt[base + j] : 0;
        pre[j] = s; s += v[j];
    }
    int lane = t & 31, w = t >> 5;
    int x = s;
#pragma unroll
    for (int o = 1; o < 32; o <<= 1) {
        int y = __shfl_up_sync(0xffffffffu, x, o);
        if (lane >= o) x += y;
    }
    __shared__ int wsum[8];
    if (lane == 31) wsum[w] = x;
    __syncthreads();
    if (t == 0) {
        int a = 0;
        for (int i = 0; i < 8; i++) { int tmp = wsum[i]; wsum[i] = a; a += tmp; }
    }
    __syncthreads();
    int excl = x - s + wsum[w] + g_boff[b];
#pragma unroll
    for (int j = 0; j < 4; j++) {
        if (base + j < NN) {
            int o = excl + pre[j];
            g_off[base + j] = o;
            g_cur[base + j] = o;
            g_inv[base + j] = 1.f / fmaxf((float)v[j], 1.f);
        }
    }
}

// scatter edges into CSR segments
__global__ __launch_bounds__(256) void scatter_kernel(
    const int* __restrict__ ei, const float* __restrict__ ea) {
    int e = blockIdx.x * 256 + threadIdx.x;
    if (e >= NE) return;
    int s = ei[e];
    int d = ei[NE + e];
    float u = fminf(fmaxf(ea[e], 0.f), 1.f);
    int slot = atomicAdd(&g_cur[d], 1);
    g_edges[slot] = make_float2(__int_as_float(s), u);
}

// ---------------------------------------------------------------------------
// GEMM1: scalar FFMA, K-chunk 32 (smem ~23KB, low regs -> high occupancy).
// [xs0|xs1] -> g_xs01, root part -> g_xroot
__global__ __launch_bounds__(256) void gemm1_kernel(
    const float* __restrict__ x, const float* __restrict__ W1,
    const float* __restrict__ root1) {
    __shared__ float xt[32][132];   // [k][node], padded
    __shared__ float wc[32][48];    // [k][col]

    const int tid = threadIdx.x;
    const int cg  = tid & 7;        // col group -> cols cg*6 .. cg*6+5
    const int ng  = tid >> 3;       // node group -> nodes 4*ng .. 4*ng+3
    const int n0  = blockIdx.x * 128;

    float acc[24];
#pragma unroll
    for (int i = 0; i < 24; i++) acc[i] = 0.f;

    for (int k0 = 0; k0 < F_IN; k0 += 32) {
        // stage x: 128 nodes x 32 k, transposed into xt[k][node]
        {
            int nl = tid >> 1;              // local node 0..127
            int n  = n0 + nl;
            int half = tid & 1;
#pragma unroll
            for (int i = 0; i < 4; i++) {
                int q = half * 4 + i;       // float4 index within 32 k
                float4 v = make_float4(0.f, 0.f, 0.f, 0.f);
                if (n < NN)
                    v = *(const float4*)(x + (size_t)n * F_IN + k0 + q * 4);
                xt[q * 4 + 0][nl] = v.x;
                xt[q * 4 + 1][nl] = v.y;
                xt[q * 4 + 2][nl] = v.z;
                xt[q * 4 + 3][nl] = v.w;
            }
        }
        // stage combined weights: wc[kk][c]
        for (int i = tid; i < 32 * 48; i += 256) {
            int kk = i / 48, c = i % 48;
            int f = k0 + kk;
            float w;
            if (c < 32) w = W1[(c >> 4) * (F_IN * HID) + f * HID + (c & 15)];
            else        w = root1[f * HID + (c - 32)];
            wc[kk][c] = w;
        }
        __syncthreads();

#pragma unroll 4
        for (int kk = 0; kk < 32; kk++) {
            float2 xa = *(const float2*)&xt[kk][ng * 4];
            float2 xb = *(const float2*)&xt[kk][ng * 4 + 2];
#pragma unroll
            for (int j = 0; j < 6; j++) {
                float w = wc[kk][cg * 6 + j];
                acc[j]      += xa.x * w;
                acc[6 + j]  += xa.y * w;
                acc[12 + j] += xb.x * w;
                acc[18 + j] += xb.y * w;
            }
        }
        __syncthreads();
    }

#pragma unroll
    for (int v = 0; v < 4; v++) {
        int n = n0 + ng * 4 + v;
        if (n < NN) {
#pragma unroll
            for (int j = 0; j < 6; j++) {
                int c = cg * 6 + j;
                float val = acc[v * 6 + j];
                if (c < 32) g_xs01[(size_t)n * 32 + c] = val;
                else        g_xroot[(size_t)n * 16 + (c - 32)] = val;
            }
        }
    }
}

// ---------------------------------------------------------------------------
// Pull pass 1 + node update: warp per dst node, half-warp streams, 2x unroll.
__global__ __launch_bounds__(256) void pass1_kernel(const float* __restrict__ bias1) {
    int n = blockIdx.x * 8 + (threadIdx.x >> 5);
    if (n >= NN) return;
    int lane = threadIdx.x & 31;
    int f = lane & 15, half = lane >> 4;
    int beg = g_off[n];
    int deg = g_cnt[n];

    const float2 z = make_float2(0.f, 0.f);
    float accA = 0.f, accB = 0.f;
    float2 e0 = (half < deg)     ? g_edges[beg + half]     : z;
    float2 e1 = (half + 2 < deg) ? g_edges[beg + half + 2] : z;
    for (int i = half; i < deg; i += 4) {
        float2 p0 = (i + 4 < deg) ? g_edges[beg + i + 4] : z;
        float2 p1 = (i + 6 < deg) ? g_edges[beg + i + 6] : z;
        {
            int s = __float_as_int(e0.x);
            float u = e0.y;
            const float* p = g_xs01 + (size_t)s * 32;
            accA += (1.f - u) * __ldg(p + f) + u * __ldg(p + 16 + f);
        }
        if (i + 2 < deg) {
            int s = __float_as_int(e1.x);
            float u = e1.y;
            const float* p = g_xs01 + (size_t)s * 32;
            accB += (1.f - u) * __ldg(p + f) + u * __ldg(p + 16 + f);
        }
        e0 = p0; e1 = p1;
    }
    float acc = accA + accB;
    acc += __shfl_xor_sync(0xffffffffu, acc, 16);
    if (half == 0) {
        float v = acc * g_inv[n] + g_xroot[(size_t)n * 16 + f] + bias1[f];
        g_h[(size_t)n * 16 + f] = v > 0.f ? v : expm1f(v);
    }
}

// ---------------------------------------------------------------------------
// Pull pass 2 + final GEMM + log_softmax, same 2x stream unroll.
__global__ __launch_bounds__(256) void pass2_final_kernel(
    const float* __restrict__ W2, const float* __restrict__ root2,
    const float* __restrict__ bias2, float* __restrict__ out) {
    const int lane = threadIdx.x & 31;
    const int f = lane & 15, half = lane >> 4;
    const int wid = blockIdx.x * 8 + (threadIdx.x >> 5);
    const int nwarps = gridDim.x * 8;

    float w0col[16], w1col[16], rcol[16];
#pragma unroll
    for (int k = 0; k < 16; k++) {
        w0col[k] = W2[k * NC + lane];
        w1col[k] = W2[16 * NC + k * NC + lane];
        rcol[k]  = root2[k * NC + lane];
    }
    const float bias = bias2[lane];
    const float2 z = make_float2(0.f, 0.f);

    for (int n = wid; n < NN; n += nwarps) {
        int beg = g_off[n];
        int deg = g_cnt[n];
        float a0A = 0.f, a1A = 0.f, a0B = 0.f, a1B = 0.f;
        float2 e0 = (half < deg)     ? g_edges[beg + half]     : z;
        float2 e1 = (half + 2 < deg) ? g_edges[beg + half + 2] : z;
        for (int i = half; i < deg; i += 4) {
            float2 p0 = (i + 4 < deg) ? g_edges[beg + i + 4] : z;
            float2 p1 = (i + 6 < deg) ? g_edges[beg + i + 6] : z;
            {
                int s = __float_as_int(e0.x);
                float u = e0.y;
                float hv = __ldg(g_h + (size_t)s * 16 + f);
                a0A += (1.f - u) * hv;
                a1A += u * hv;
            }
            if (i + 2 < deg) {
                int s = __float_as_int(e1.x);
                float u = e1.y;
                float hv = __ldg(g_h + (size_t)s * 16 + f);
                a0B += (1.f - u) * hv;
                a1B += u * hv;
            }
            e0 = p0; e1 = p1;
        }
        float a0 = a0A + a0B, a1 = a1A + a1B;
        a0 += __shfl_xor_sync(0xffffffffu, a0, 16);
        a1 += __shfl_xor_sync(0xffffffffu, a1, 16);
        float hn = g_h[(size_t)n * 16 + f];

        float oagg = 0.f, oroot = 0.f;
#pragma unroll
        for (int k = 0; k < 16; k++) {
            float a0k = __shfl_sync(0xffffffffu, a0, k);
            float a1k = __shfl_sync(0xffffffffu, a1, k);
            float hk  = __shfl_sync(0xffffffffu, hn, k);
            oagg  += a0k * w0col[k] + a1k * w1col[k];
            oroot += hk * rcol[k];
        }
        float o = oagg * g_inv[n] + oroot + bias;

        float m = o;
#pragma unroll
        for (int off = 16; off; off >>= 1)
            m = fmaxf(m, __shfl_xor_sync(0xffffffffu, m, off));
        float ex = __expf(o - m);
        float ssum = ex;
#pragma unroll
        for (int off = 16; off; off >>= 1)
            ssum += __shfl_xor_sync(0xffffffffu, ssum, off);
        out[(size_t)n * 32 + lane] = o - m - logf(ssum);
    }
}

// ---------------------------------------------------------------------------
extern "C" void kernel_launch(void* const* d_in, const int* in_sizes, int n_in,
                              void* d_out, int out_size) {
    const float* x     = (const float*)d_in[0];
    const float* ea    = (const float*)d_in[1];
    const float* W1    = (const float*)d_in[2];
    const float* root1 = (const float*)d_in[3];
    const float* bias1 = (const float*)d_in[4];
    const float* W2    = (const float*)d_in[5];
    const float* root2 = (const float*)d_in[6];
    const float* bias2 = (const float*)d_in[7];
    const int*   ei    = (const int*)d_in[8];
    float* out = (float*)d_out;

    // side stream + events for capture fork/join (host-side handles, created
    // once; deterministic captured work each call)
    static cudaStream_t s1 = [] { cudaStream_t s; cudaStreamCreate(&s); return s; }();
    static cudaEvent_t ev_fork = [] { cudaEvent_t e; cudaEventCreateWithFlags(&e, cudaEventDisableTiming); return e; }();
    static cudaEvent_t ev_join = [] { cudaEvent_t e; cudaEventCreateWithFlags(&e, cudaEventDisableTiming); return e; }();

    // fork point: gemm1 depends only on kernel inputs
    cudaEventRecord(ev_fork, 0);

    // main stream: CSR build chain
    zero_kernel<<<(NN + 255) / 256, 256>>>();
    hist_kernel<<<(NE + 255) / 256, 256>>>(ei);
    scanA_kernel<<<NSCB, 256>>>();

    // side stream: gemm1 (submission #4 -> profiled slot)
    cudaStreamWaitEvent(s1, ev_fork, 0);
    gemm1_kernel<<<(NN + 127) / 128, 256, 0, s1>>>(x, W1, root1);
    cudaEventRecord(ev_join, s1);

    scanB_kernel<<<1, 32>>>();
    scanC_kernel<<<NSCB, 256>>>();
    scatter_kernel<<<(NE + 255) / 256, 256>>>(ei, ea);

    // join: pass1 needs both gemm1 output and the CSR
    cudaStreamWaitEvent(0, ev_join, 0);
    pass1_kernel<<<(NN + 7) / 8, 256>>>(bias1);
    pass2_final_kernel<<<1850, 256>>>(W2, root2, bias2, out);
}